// round 6
// baseline (speedup 1.0000x reference)
#include <cuda_runtime.h>
#include <cstdint>

// ---------------------------------------------------------------------------
// Problem constants
// ---------------------------------------------------------------------------
#define BATCH 8
#define IMG   256
#define CCH   16
#define HID   128
#define NPIX  (BATCH * IMG * IMG)          // 524288 pixels
#define STATE_ELEMS (NPIX * CCH)
#define STEPS 32
#define LIST_CAP (NPIX / 2 + 8192)

typedef unsigned long long u64;

__device__ float g_state[2][STATE_ELEMS];
__device__ int g_list[STEPS][LIST_CAP];
__device__ int g_ilist[STEPS][LIST_CAP];
__device__ int g_cnt[STEPS];
__device__ int g_icnt[STEPS];

// weights in constant memory: warp-uniform access -> ULDC on uniform pipe,
// zero L1TEX traffic (the measured bottleneck)
__constant__ float c_w0[48 * HID];   // 24 KB
__constant__ float c_w1[HID * CCH];  //  8 KB
__constant__ float c_b[HID];
__constant__ float c_p0[144];
__constant__ float c_p1[144];

struct KeyArr { uint32_t k0[STEPS]; uint32_t k1[STEPS]; };

// ---------------------------------------------------------------------------
// packed f32x2 helpers (bit-exact: two independent rn fp32 FMAs)
// ---------------------------------------------------------------------------
static __device__ __forceinline__ u64 pack2dup(float x) {
    u64 r; asm("mov.b64 %0, {%1, %1};" : "=l"(r) : "f"(x)); return r;
}
static __device__ __forceinline__ void ffma2(u64& acc, u64 a, u64 b) {
    asm("fma.rn.f32x2 %0, %1, %2, %0;" : "+l"(acc) : "l"(a), "l"(b));
}
static __device__ __forceinline__ float2 unpack2(u64 v) {
    float2 f; asm("mov.b64 {%0, %1}, %2;" : "=f"(f.x), "=f"(f.y) : "l"(v)); return f;
}

// ---------------------------------------------------------------------------
// Threefry-2x32 (20 rounds) — exact JAX implementation
// ---------------------------------------------------------------------------
static __host__ __device__ __forceinline__ uint32_t tf_rotl(uint32_t v, int r) {
    return (v << r) | (v >> (32 - r));
}
static __host__ __device__ __forceinline__ void threefry2x32(
    uint32_t k0, uint32_t k1, uint32_t x0, uint32_t x1,
    uint32_t& o0, uint32_t& o1)
{
    uint32_t ks2 = k0 ^ k1 ^ 0x1BD11BDAu;
    x0 += k0; x1 += k1;
    x0 += x1; x1 = tf_rotl(x1, 13); x1 ^= x0;
    x0 += x1; x1 = tf_rotl(x1, 15); x1 ^= x0;
    x0 += x1; x1 = tf_rotl(x1, 26); x1 ^= x0;
    x0 += x1; x1 = tf_rotl(x1,  6); x1 ^= x0;
    x0 += k1; x1 += ks2 + 1u;
    x0 += x1; x1 = tf_rotl(x1, 17); x1 ^= x0;
    x0 += x1; x1 = tf_rotl(x1, 29); x1 ^= x0;
    x0 += x1; x1 = tf_rotl(x1, 16); x1 ^= x0;
    x0 += x1; x1 = tf_rotl(x1, 24); x1 ^= x0;
    x0 += ks2; x1 += k0 + 2u;
    x0 += x1; x1 = tf_rotl(x1, 13); x1 ^= x0;
    x0 += x1; x1 = tf_rotl(x1, 15); x1 ^= x0;
    x0 += x1; x1 = tf_rotl(x1, 26); x1 ^= x0;
    x0 += x1; x1 = tf_rotl(x1,  6); x1 ^= x0;
    x0 += k0; x1 += k1 + 3u;
    x0 += x1; x1 = tf_rotl(x1, 17); x1 ^= x0;
    x0 += x1; x1 = tf_rotl(x1, 29); x1 ^= x0;
    x0 += x1; x1 = tf_rotl(x1, 16); x1 ^= x0;
    x0 += x1; x1 = tf_rotl(x1, 24); x1 ^= x0;
    x0 += k1; x1 += ks2 + 4u;
    x0 += x1; x1 = tf_rotl(x1, 13); x1 ^= x0;
    x0 += x1; x1 = tf_rotl(x1, 15); x1 ^= x0;
    x0 += x1; x1 = tf_rotl(x1, 26); x1 ^= x0;
    x0 += x1; x1 = tf_rotl(x1,  6); x1 ^= x0;
    x0 += ks2; x1 += k0 + 5u;
    o0 = x0; o1 = x1;
}

// ---------------------------------------------------------------------------
// Pack: NCHW -> NHWC state 0; zero list counters
// ---------------------------------------------------------------------------
__global__ void nca_pack_kernel(const float* __restrict__ x)
{
    int p = blockIdx.x * 256 + threadIdx.x;
    if (blockIdx.x == 0 && threadIdx.x < STEPS) {
        g_cnt[threadIdx.x] = 0;
        g_icnt[threadIdx.x] = 0;
    }
    if (p >= NPIX) return;
    int b  = p >> 16;
    int hw = p & 65535;
    float v[CCH];
#pragma unroll
    for (int c = 0; c < CCH; ++c)
        v[c] = x[((size_t)(b * CCH + c) << 16) + hw];
    float4* dst = reinterpret_cast<float4*>(g_state[0] + ((size_t)p << 4));
    dst[0] = make_float4(v[0],  v[1],  v[2],  v[3]);
    dst[1] = make_float4(v[4],  v[5],  v[6],  v[7]);
    dst[2] = make_float4(v[8],  v[9],  v[10], v[11]);
    dst[3] = make_float4(v[12], v[13], v[14], v[15]);
}

// ---------------------------------------------------------------------------
// All 32 fire masks in one pass
// ---------------------------------------------------------------------------
__global__ void nca_maskall_kernel(KeyArr keys)
{
    int p = blockIdx.x * 256 + threadIdx.x;
    const int lane = threadIdx.x & 31;

#pragma unroll 1
    for (int s = 0; s < STEPS; ++s) {
        uint32_t r0, r1;
        threefry2x32(keys.k0[s], keys.k1[s], 0u, (uint32_t)p, r0, r1);
        uint32_t bits = r0 ^ r1;
        float u = __uint_as_float((bits >> 9) | 0x3f800000u) - 1.0f;
        bool active = (u <= 0.5f);

        unsigned ball = __ballot_sync(0xffffffffu, active);
        int nact = __popc(ball);
        int rank = __popc(ball & ((1u << lane) - 1u));
        int baseA = 0, baseI = 0;
        if (lane == 0) {
            if (nact > 0)  baseA = atomicAdd(&g_cnt[s], nact);
            if (nact < 32) baseI = atomicAdd(&g_icnt[s], 32 - nact);
        }
        baseA = __shfl_sync(0xffffffffu, baseA, 0);
        baseI = __shfl_sync(0xffffffffu, baseI, 0);
        if (active) g_list[s][baseA + rank] = p;
        else        g_ilist[s][baseI + (lane - rank)] = p;
    }
}

// ---------------------------------------------------------------------------
// Per-step fused kernel: active MLP blocks + inactive copy blocks
// ---------------------------------------------------------------------------
#define UPD_BLOCKS  512
#define CPY_BLOCKS  256
#define TOT_BLOCKS  (UPD_BLOCKS + CPY_BLOCKS)

__global__ void __launch_bounds__(128)
nca_step_kernel(int src, int step)
{
    const float* cur = g_state[src];
    float*       nxt = g_state[src ^ 1];
    const int tid = threadIdx.x;

    // ---------------- inactive copy-through blocks ----------------
    if (blockIdx.x >= UPD_BLOCKS) {
        const int icnt = g_icnt[step];
        const int* il = g_ilist[step];
        for (int i = (blockIdx.x - UPD_BLOCKS) * 128 + tid; i < icnt;
             i += CPY_BLOCKS * 128) {
            int p = il[i];
            const float4* s = reinterpret_cast<const float4*>(cur + ((size_t)p << 4));
            float4* d = reinterpret_cast<float4*>(nxt + ((size_t)p << 4));
            d[0] = s[0]; d[1] = s[1]; d[2] = s[2]; d[3] = s[3];
        }
        return;
    }

    // ---------------- active MLP blocks ----------------
    const int count = g_cnt[step];
    const int* al = g_list[step];

#pragma unroll 1
    for (int base = blockIdx.x * 256; base < count; base += UPD_BLOCKS * 256) {
        int iA = base + tid;
        if (iA >= count) continue;
        int iB = base + 128 + tid;
        int pA = al[iA];
        int pB = (iB < count) ? al[iB] : pA;   // duplicate is benign

        const float* baseA = cur + ((size_t)(pA >> 16) << 20);
        const float* baseB = cur + ((size_t)(pB >> 16) << 20);
        const int hA = (pA >> 8) & 255, wA = pA & 255;
        const int hB = (pB >> 8) & 255, wB = pB & 255;

        // ---- perception for BOTH pixels, tap-outer (shared tap weights) ----
        float percA[48], percB[48];
        {
            u64 cA0[8], cA1[8], cB0[8], cB1[8];
#pragma unroll
            for (int k = 0; k < 8; ++k) { cA0[k]=0ull; cA1[k]=0ull; cB0[k]=0ull; cB1[k]=0ull; }

#pragma unroll
            for (int dh = -1; dh <= 1; ++dh) {
                int hhA = hA + dh; hhA = (hhA < 0) ? 1 : ((hhA > 255) ? 254 : hhA);
                int hhB = hB + dh; hhB = (hhB < 0) ? 1 : ((hhB > 255) ? 254 : hhB);
#pragma unroll
                for (int dw = -1; dw <= 1; ++dw) {
                    int wwA = wA + dw; wwA = (wwA < 0) ? 1 : ((wwA > 255) ? 254 : wwA);
                    int wwB = wB + dw; wwB = (wwB < 0) ? 1 : ((wwB > 255) ? 254 : wwB);
                    const ulonglong2* pxA = reinterpret_cast<const ulonglong2*>(
                        baseA + (((size_t)((hhA << 8) | wwA)) << 4));
                    const ulonglong2* pxB = reinterpret_cast<const ulonglong2*>(
                        baseB + (((size_t)((hhB << 8) | wwB)) << 4));
                    ulonglong2 qa0 = pxA[0], qa1 = pxA[1], qa2 = pxA[2], qa3 = pxA[3];
                    ulonglong2 qb0 = pxB[0], qb1 = pxB[1], qb2 = pxB[2], qb3 = pxB[3];
                    u64 va[8] = {qa0.x,qa0.y,qa1.x,qa1.y,qa2.x,qa2.y,qa3.x,qa3.y};
                    u64 vb[8] = {qb0.x,qb0.y,qb1.x,qb1.y,qb2.x,qb2.y,qb3.x,qb3.y};
                    const int tap = (dh + 1) * 3 + (dw + 1);
                    const ulonglong2* wp0 = reinterpret_cast<const ulonglong2*>(c_p0 + tap * 16);
                    const ulonglong2* wp1 = reinterpret_cast<const ulonglong2*>(c_p1 + tap * 16);
#pragma unroll
                    for (int q = 0; q < 4; ++q) {
                        ulonglong2 t0 = wp0[q], t1 = wp1[q];
                        ffma2(cA0[2*q],   va[2*q],   t0.x);
                        ffma2(cA0[2*q+1], va[2*q+1], t0.y);
                        ffma2(cA1[2*q],   va[2*q],   t1.x);
                        ffma2(cA1[2*q+1], va[2*q+1], t1.y);
                        ffma2(cB0[2*q],   vb[2*q],   t0.x);
                        ffma2(cB0[2*q+1], vb[2*q+1], t0.y);
                        ffma2(cB1[2*q],   vb[2*q],   t1.x);
                        ffma2(cB1[2*q+1], vb[2*q+1], t1.y);
                    }
                    if (dh == 0 && dw == 0) {
#pragma unroll
                        for (int q = 0; q < 8; ++q) {
                            float2 fa = unpack2(va[q]);
                            float2 fb = unpack2(vb[q]);
                            percA[2*q] = fa.x; percA[2*q+1] = fa.y;
                            percB[2*q] = fb.x; percB[2*q+1] = fb.y;
                        }
                    }
                }
            }
#pragma unroll
            for (int k = 0; k < 8; ++k) {
                float2 a0 = unpack2(cA0[k]);
                float2 a1 = unpack2(cA1[k]);
                float2 b0 = unpack2(cB0[k]);
                float2 b1 = unpack2(cB1[k]);
                percA[16 + 2*k] = a0.x; percA[16 + 2*k + 1] = a0.y;
                percA[32 + 2*k] = a1.x; percA[32 + 2*k + 1] = a1.y;
                percB[16 + 2*k] = b0.x; percB[16 + 2*k + 1] = b0.y;
                percB[32 + 2*k] = b1.x; percB[32 + 2*k + 1] = b1.y;
            }
        }

        // ---- fused MLP: 8 chunks of 16 hidden units, 2 pixels ----
        u64 dxA[8], dxB[8];
#pragma unroll
        for (int k = 0; k < 8; ++k) { dxA[k] = 0ull; dxB[k] = 0ull; }

#pragma unroll 1
        for (int chunk = 0; chunk < 8; ++chunk) {
            u64 hA2[8], hB2[8];
            {
                const ulonglong2* bv = reinterpret_cast<const ulonglong2*>(c_b + chunk * 16);
#pragma unroll
                for (int q = 0; q < 4; ++q) {
                    ulonglong2 t = bv[q];
                    hA2[2*q] = t.x; hA2[2*q+1] = t.y;
                    hB2[2*q] = t.x; hB2[2*q+1] = t.y;
                }
            }
#pragma unroll
            for (int c = 0; c < 48; ++c) {
                u64 pa2 = pack2dup(percA[c]);
                u64 pb2 = pack2dup(percB[c]);
                const ulonglong2* wr = reinterpret_cast<const ulonglong2*>(
                    c_w0 + c * HID + chunk * 16);
#pragma unroll
                for (int q = 0; q < 4; ++q) {
                    ulonglong2 t = wr[q];
                    ffma2(hA2[2*q],   pa2, t.x);
                    ffma2(hA2[2*q+1], pa2, t.y);
                    ffma2(hB2[2*q],   pb2, t.x);
                    ffma2(hB2[2*q+1], pb2, t.y);
                }
            }
            // relu + second layer
#pragma unroll
            for (int jj = 0; jj < 4; ++jj) {
                float2 ha = unpack2(hA2[2*jj]);
                float2 ha2 = unpack2(hA2[2*jj+1]);
                float2 hb = unpack2(hB2[2*jj]);
                float2 hb2 = unpack2(hB2[2*jj+1]);
                int j0 = chunk * 16 + 4 * jj;
                const ulonglong2* w10 = reinterpret_cast<const ulonglong2*>(c_w1 + ((j0+0) << 4));
                const ulonglong2* w11 = reinterpret_cast<const ulonglong2*>(c_w1 + ((j0+1) << 4));
                const ulonglong2* w12 = reinterpret_cast<const ulonglong2*>(c_w1 + ((j0+2) << 4));
                const ulonglong2* w13 = reinterpret_cast<const ulonglong2*>(c_w1 + ((j0+3) << 4));
                u64 dA0 = pack2dup(fmaxf(ha.x,  0.f));
                u64 dA1 = pack2dup(fmaxf(ha.y,  0.f));
                u64 dA2 = pack2dup(fmaxf(ha2.x, 0.f));
                u64 dA3 = pack2dup(fmaxf(ha2.y, 0.f));
                u64 dB0 = pack2dup(fmaxf(hb.x,  0.f));
                u64 dB1 = pack2dup(fmaxf(hb.y,  0.f));
                u64 dB2 = pack2dup(fmaxf(hb2.x, 0.f));
                u64 dB3 = pack2dup(fmaxf(hb2.y, 0.f));
#pragma unroll
                for (int q = 0; q < 4; ++q) {
                    ulonglong2 t0 = w10[q];
                    ffma2(dxA[2*q],   dA0, t0.x);
                    ffma2(dxA[2*q+1], dA0, t0.y);
                    ffma2(dxB[2*q],   dB0, t0.x);
                    ffma2(dxB[2*q+1], dB0, t0.y);
                }
#pragma unroll
                for (int q = 0; q < 4; ++q) {
                    ulonglong2 t1 = w11[q];
                    ffma2(dxA[2*q],   dA1, t1.x);
                    ffma2(dxA[2*q+1], dA1, t1.y);
                    ffma2(dxB[2*q],   dB1, t1.x);
                    ffma2(dxB[2*q+1], dB1, t1.y);
                }
#pragma unroll
                for (int q = 0; q < 4; ++q) {
                    ulonglong2 t2 = w12[q];
                    ffma2(dxA[2*q],   dA2, t2.x);
                    ffma2(dxA[2*q+1], dA2, t2.y);
                    ffma2(dxB[2*q],   dB2, t2.x);
                    ffma2(dxB[2*q+1], dB2, t2.y);
                }
#pragma unroll
                for (int q = 0; q < 4; ++q) {
                    ulonglong2 t3 = w13[q];
                    ffma2(dxA[2*q],   dA3, t3.x);
                    ffma2(dxA[2*q+1], dA3, t3.y);
                    ffma2(dxB[2*q],   dB3, t3.x);
                    ffma2(dxB[2*q+1], dB3, t3.y);
                }
            }
        }

        // ---- residual update; channels 0..2 pinned ----
        float outA[CCH], outB[CCH];
#pragma unroll
        for (int k = 0; k < 8; ++k) {
            float2 da = unpack2(dxA[k]);
            float2 db = unpack2(dxB[k]);
            outA[2*k]   = percA[2*k]   + da.x;
            outA[2*k+1] = percA[2*k+1] + da.y;
            outB[2*k]   = percB[2*k]   + db.x;
            outB[2*k+1] = percB[2*k+1] + db.y;
        }
        outA[0] = percA[0]; outA[1] = percA[1]; outA[2] = percA[2];
        outB[0] = percB[0]; outB[1] = percB[1]; outB[2] = percB[2];

        float4* dA = reinterpret_cast<float4*>(nxt + ((size_t)pA << 4));
        dA[0] = make_float4(outA[0],  outA[1],  outA[2],  outA[3]);
        dA[1] = make_float4(outA[4],  outA[5],  outA[6],  outA[7]);
        dA[2] = make_float4(outA[8],  outA[9],  outA[10], outA[11]);
        dA[3] = make_float4(outA[12], outA[13], outA[14], outA[15]);
        float4* dB = reinterpret_cast<float4*>(nxt + ((size_t)pB << 4));
        dB[0] = make_float4(outB[0],  outB[1],  outB[2],  outB[3]);
        dB[1] = make_float4(outB[4],  outB[5],  outB[6],  outB[7]);
        dB[2] = make_float4(outB[8],  outB[9],  outB[10], outB[11]);
        dB[3] = make_float4(outB[12], outB[13], outB[14], outB[15]);
    }
}

// ---------------------------------------------------------------------------
// Unpack
// ---------------------------------------------------------------------------
__global__ void nca_unpack_kernel(float* __restrict__ out)
{
    int p = blockIdx.x * 256 + threadIdx.x;
    if (p >= NPIX) return;
    int b  = p >> 16;
    int hw = p & 65535;
    const float4* src = reinterpret_cast<const float4*>(g_state[0] + ((size_t)p << 4));
    float4 a0 = src[0], a1 = src[1], a2 = src[2], a3 = src[3];
    float v[CCH] = {a0.x,a0.y,a0.z,a0.w, a1.x,a1.y,a1.z,a1.w,
                    a2.x,a2.y,a2.z,a2.w, a3.x,a3.y,a3.z,a3.w};
    out[((size_t)b << 16) + hw] = v[3];
    float* xf = out + NPIX;
#pragma unroll
    for (int c = 0; c < CCH; ++c)
        xf[((size_t)(b * CCH + c) << 16) + hw] = v[c];
}

// ---------------------------------------------------------------------------
// Launch
// ---------------------------------------------------------------------------
extern "C" void kernel_launch(void* const* d_in, const int* in_sizes, int n_in,
                              void* d_out, int out_size)
{
    const float* x      = (const float*)d_in[0];
    const float* w_p0   = (const float*)d_in[1];
    const float* w_p1   = (const float*)d_in[2];
    const float* w_fc0  = (const float*)d_in[3];
    const float* b_fc0  = (const float*)d_in[4];
    const float* w_fc1  = (const float*)d_in[5];
    float* out = (float*)d_out;

    KeyArr keys;
    for (int j = 0; j < STEPS; ++j) {
        uint32_t a, b;
        threefry2x32(0u, 42u, 0u, (uint32_t)j, a, b);
        keys.k0[j] = a; keys.k1[j] = b;
    }

    // stage weights into constant memory (async D2D, graph-capturable)
    cudaMemcpyToSymbolAsync(c_w0, w_fc0, 48 * HID * sizeof(float), 0,
                            cudaMemcpyDeviceToDevice, 0);
    cudaMemcpyToSymbolAsync(c_w1, w_fc1, HID * CCH * sizeof(float), 0,
                            cudaMemcpyDeviceToDevice, 0);
    cudaMemcpyToSymbolAsync(c_b, b_fc0, HID * sizeof(float), 0,
                            cudaMemcpyDeviceToDevice, 0);
    cudaMemcpyToSymbolAsync(c_p0, w_p0, 144 * sizeof(float), 0,
                            cudaMemcpyDeviceToDevice, 0);
    cudaMemcpyToSymbolAsync(c_p1, w_p1, 144 * sizeof(float), 0,
                            cudaMemcpyDeviceToDevice, 0);

    nca_pack_kernel<<<NPIX / 256, 256>>>(x);
    nca_maskall_kernel<<<NPIX / 256, 256>>>(keys);
    for (int s = 0; s < STEPS; ++s) {
        nca_step_kernel<<<TOT_BLOCKS, 128>>>(s & 1, s);
    }
    nca_unpack_kernel<<<NPIX / 256, 256>>>(out);
}

// round 7
// speedup vs baseline: 5.3201x; 5.3201x over previous
#include <cuda_runtime.h>
#include <cstdint>

// ---------------------------------------------------------------------------
// Problem constants
// ---------------------------------------------------------------------------
#define BATCH 8
#define IMG   256
#define CCH   16
#define HID   128
#define NPIX  (BATCH * IMG * IMG)          // 524288 pixels
#define STATE_ELEMS (NPIX * CCH)
#define STEPS 32
#define LIST_CAP (NPIX / 2 + 8192)

typedef unsigned long long u64;

__device__ float g_state[2][STATE_ELEMS];
__device__ int g_list[STEPS][LIST_CAP];
__device__ int g_ilist[STEPS][LIST_CAP];
__device__ int g_cnt[STEPS];
__device__ int g_icnt[STEPS];

struct KeyArr { uint32_t k0[STEPS]; uint32_t k1[STEPS]; };

// ---------------------------------------------------------------------------
// packed f32x2 helpers (bit-exact: two independent rn fp32 FMAs)
// ---------------------------------------------------------------------------
static __device__ __forceinline__ u64 pack2dup(float x) {
    u64 r; asm("mov.b64 %0, {%1, %1};" : "=l"(r) : "f"(x)); return r;
}
static __device__ __forceinline__ void ffma2(u64& acc, u64 a, u64 b) {
    asm("fma.rn.f32x2 %0, %1, %2, %0;" : "+l"(acc) : "l"(a), "l"(b));
}
static __device__ __forceinline__ float2 unpack2(u64 v) {
    float2 f; asm("mov.b64 {%0, %1}, %2;" : "=f"(f.x), "=f"(f.y) : "l"(v)); return f;
}

// ---------------------------------------------------------------------------
// Threefry-2x32 (20 rounds) — exact JAX implementation
// ---------------------------------------------------------------------------
static __host__ __device__ __forceinline__ uint32_t tf_rotl(uint32_t v, int r) {
    return (v << r) | (v >> (32 - r));
}
static __host__ __device__ __forceinline__ void threefry2x32(
    uint32_t k0, uint32_t k1, uint32_t x0, uint32_t x1,
    uint32_t& o0, uint32_t& o1)
{
    uint32_t ks2 = k0 ^ k1 ^ 0x1BD11BDAu;
    x0 += k0; x1 += k1;
    x0 += x1; x1 = tf_rotl(x1, 13); x1 ^= x0;
    x0 += x1; x1 = tf_rotl(x1, 15); x1 ^= x0;
    x0 += x1; x1 = tf_rotl(x1, 26); x1 ^= x0;
    x0 += x1; x1 = tf_rotl(x1,  6); x1 ^= x0;
    x0 += k1; x1 += ks2 + 1u;
    x0 += x1; x1 = tf_rotl(x1, 17); x1 ^= x0;
    x0 += x1; x1 = tf_rotl(x1, 29); x1 ^= x0;
    x0 += x1; x1 = tf_rotl(x1, 16); x1 ^= x0;
    x0 += x1; x1 = tf_rotl(x1, 24); x1 ^= x0;
    x0 += ks2; x1 += k0 + 2u;
    x0 += x1; x1 = tf_rotl(x1, 13); x1 ^= x0;
    x0 += x1; x1 = tf_rotl(x1, 15); x1 ^= x0;
    x0 += x1; x1 = tf_rotl(x1, 26); x1 ^= x0;
    x0 += x1; x1 = tf_rotl(x1,  6); x1 ^= x0;
    x0 += k0; x1 += k1 + 3u;
    x0 += x1; x1 = tf_rotl(x1, 17); x1 ^= x0;
    x0 += x1; x1 = tf_rotl(x1, 29); x1 ^= x0;
    x0 += x1; x1 = tf_rotl(x1, 16); x1 ^= x0;
    x0 += x1; x1 = tf_rotl(x1, 24); x1 ^= x0;
    x0 += k1; x1 += ks2 + 4u;
    x0 += x1; x1 = tf_rotl(x1, 13); x1 ^= x0;
    x0 += x1; x1 = tf_rotl(x1, 15); x1 ^= x0;
    x0 += x1; x1 = tf_rotl(x1, 26); x1 ^= x0;
    x0 += x1; x1 = tf_rotl(x1,  6); x1 ^= x0;
    x0 += ks2; x1 += k0 + 5u;
    o0 = x0; o1 = x1;
}

// ---------------------------------------------------------------------------
// Pack: NCHW -> NHWC state 0; zero list counters
// ---------------------------------------------------------------------------
__global__ void nca_pack_kernel(const float* __restrict__ x)
{
    int p = blockIdx.x * 256 + threadIdx.x;
    if (blockIdx.x == 0 && threadIdx.x < STEPS) {
        g_cnt[threadIdx.x] = 0;
        g_icnt[threadIdx.x] = 0;
    }
    if (p >= NPIX) return;
    int b  = p >> 16;
    int hw = p & 65535;
    float v[CCH];
#pragma unroll
    for (int c = 0; c < CCH; ++c)
        v[c] = x[((size_t)(b * CCH + c) << 16) + hw];
    float4* dst = reinterpret_cast<float4*>(g_state[0] + ((size_t)p << 4));
    dst[0] = make_float4(v[0],  v[1],  v[2],  v[3]);
    dst[1] = make_float4(v[4],  v[5],  v[6],  v[7]);
    dst[2] = make_float4(v[8],  v[9],  v[10], v[11]);
    dst[3] = make_float4(v[12], v[13], v[14], v[15]);
}

// ---------------------------------------------------------------------------
// All 32 fire masks in one pass
// ---------------------------------------------------------------------------
__global__ void nca_maskall_kernel(KeyArr keys)
{
    int p = blockIdx.x * 256 + threadIdx.x;
    const int lane = threadIdx.x & 31;

#pragma unroll 1
    for (int s = 0; s < STEPS; ++s) {
        uint32_t r0, r1;
        threefry2x32(keys.k0[s], keys.k1[s], 0u, (uint32_t)p, r0, r1);
        uint32_t bits = r0 ^ r1;
        float u = __uint_as_float((bits >> 9) | 0x3f800000u) - 1.0f;
        bool active = (u <= 0.5f);

        unsigned ball = __ballot_sync(0xffffffffu, active);
        int nact = __popc(ball);
        int rank = __popc(ball & ((1u << lane) - 1u));
        int baseA = 0, baseI = 0;
        if (lane == 0) {
            if (nact > 0)  baseA = atomicAdd(&g_cnt[s], nact);
            if (nact < 32) baseI = atomicAdd(&g_icnt[s], 32 - nact);
        }
        baseA = __shfl_sync(0xffffffffu, baseA, 0);
        baseI = __shfl_sync(0xffffffffu, baseI, 0);
        if (active) g_list[s][baseA + rank] = p;
        else        g_ilist[s][baseI + (lane - rank)] = p;
    }
}

// ---------------------------------------------------------------------------
// Per-step fused kernel: active MLP blocks + inactive copy blocks.
// 1 pixel per thread, 256-thread blocks -> low regs, high occupancy.
// ---------------------------------------------------------------------------
#define SMEM_FLOATS (6144 + 2048 + 128 + 144 + 144)
#define SMEM_BYTES  (SMEM_FLOATS * 4)
#define UPD_BLOCKS  1024
#define CPY_BLOCKS  128
#define TOT_BLOCKS  (UPD_BLOCKS + CPY_BLOCKS)

__global__ void __launch_bounds__(256)
nca_step_kernel(int src, int step,
                const float* __restrict__ w_p0, const float* __restrict__ w_p1,
                const float* __restrict__ w_fc0, const float* __restrict__ b_fc0,
                const float* __restrict__ w_fc1)
{
    const float* cur = g_state[src];
    float*       nxt = g_state[src ^ 1];
    const int tid = threadIdx.x;

    // ---------------- inactive copy-through blocks ----------------
    if (blockIdx.x >= UPD_BLOCKS) {
        const int icnt = g_icnt[step];
        const int* il = g_ilist[step];
        for (int i = (blockIdx.x - UPD_BLOCKS) * 256 + tid; i < icnt;
             i += CPY_BLOCKS * 256) {
            int p = il[i];
            const float4* s = reinterpret_cast<const float4*>(cur + ((size_t)p << 4));
            float4* d = reinterpret_cast<float4*>(nxt + ((size_t)p << 4));
            d[0] = s[0]; d[1] = s[1]; d[2] = s[2]; d[3] = s[3];
        }
        return;
    }

    // ---------------- active MLP blocks ----------------
    extern __shared__ float sm[];
    float* s_w0 = sm;            // 6144
    float* s_w1 = sm + 6144;     // 2048
    float* s_b  = sm + 8192;     // 128
    float* s_p0 = sm + 8320;     // 144
    float* s_p1 = sm + 8464;     // 144

    for (int i = tid; i < 6144; i += 256) s_w0[i] = w_fc0[i];
    for (int i = tid; i < 2048; i += 256) s_w1[i] = w_fc1[i];
    if (tid < 128) s_b[tid] = b_fc0[tid];
    if (tid < 144) { s_p0[tid] = w_p0[tid]; s_p1[tid] = w_p1[tid]; }
    __syncthreads();

    const int count = g_cnt[step];
    const int* al = g_list[step];

#pragma unroll 1
    for (int i = blockIdx.x * 256 + tid; i < count; i += UPD_BLOCKS * 256) {
        int p = al[i];
        const float* base = cur + ((size_t)(p >> 16) << 20);
        const int h = (p >> 8) & 255, w = p & 255;

        // ---- perception: center + 2 depthwise 3x3 reflect convs (packed) ----
        float perc[48];
        {
            u64 c0a[8], c1a[8];
#pragma unroll
            for (int k = 0; k < 8; ++k) { c0a[k] = 0ull; c1a[k] = 0ull; }

#pragma unroll
            for (int dh = -1; dh <= 1; ++dh) {
                int hh = h + dh; hh = (hh < 0) ? 1 : ((hh > 255) ? 254 : hh);
#pragma unroll
                for (int dw = -1; dw <= 1; ++dw) {
                    int ww = w + dw; ww = (ww < 0) ? 1 : ((ww > 255) ? 254 : ww);
                    const ulonglong2* px = reinterpret_cast<const ulonglong2*>(
                        base + (((size_t)((hh << 8) | ww)) << 4));
                    ulonglong2 q0 = px[0], q1 = px[1], q2 = px[2], q3 = px[3];
                    u64 vv[8] = {q0.x,q0.y,q1.x,q1.y,q2.x,q2.y,q3.x,q3.y};
                    const int tap = (dh + 1) * 3 + (dw + 1);
                    const ulonglong2* wp0 = reinterpret_cast<const ulonglong2*>(s_p0 + tap * 16);
                    const ulonglong2* wp1 = reinterpret_cast<const ulonglong2*>(s_p1 + tap * 16);
#pragma unroll
                    for (int q = 0; q < 4; ++q) {
                        ulonglong2 t0 = wp0[q], t1 = wp1[q];
                        ffma2(c0a[2*q],   vv[2*q],   t0.x);
                        ffma2(c0a[2*q+1], vv[2*q+1], t0.y);
                        ffma2(c1a[2*q],   vv[2*q],   t1.x);
                        ffma2(c1a[2*q+1], vv[2*q+1], t1.y);
                    }
                    if (dh == 0 && dw == 0) {
#pragma unroll
                        for (int q = 0; q < 8; ++q) {
                            float2 f = unpack2(vv[q]);
                            perc[2*q] = f.x; perc[2*q+1] = f.y;
                        }
                    }
                }
            }
#pragma unroll
            for (int k = 0; k < 8; ++k) {
                float2 a = unpack2(c0a[k]);
                float2 b = unpack2(c1a[k]);
                perc[16 + 2*k] = a.x; perc[16 + 2*k + 1] = a.y;
                perc[32 + 2*k] = b.x; perc[32 + 2*k + 1] = b.y;
            }
        }

        // ---- fused MLP: 8 chunks of 16 hidden units ----
        u64 dx2[8];
#pragma unroll
        for (int k = 0; k < 8; ++k) dx2[k] = 0ull;

#pragma unroll 1
        for (int chunk = 0; chunk < 8; ++chunk) {
            u64 h2[8];
            {
                const ulonglong2* bv = reinterpret_cast<const ulonglong2*>(s_b + chunk * 16);
#pragma unroll
                for (int q = 0; q < 4; ++q) {
                    ulonglong2 t = bv[q];
                    h2[2*q] = t.x; h2[2*q+1] = t.y;
                }
            }
#pragma unroll
            for (int c = 0; c < 48; ++c) {
                u64 pc2 = pack2dup(perc[c]);
                const ulonglong2* wr = reinterpret_cast<const ulonglong2*>(
                    s_w0 + c * HID + chunk * 16);
#pragma unroll
                for (int q = 0; q < 4; ++q) {
                    ulonglong2 t = wr[q];
                    ffma2(h2[2*q],   pc2, t.x);
                    ffma2(h2[2*q+1], pc2, t.y);
                }
            }
            // relu + second layer
#pragma unroll
            for (int jj = 0; jj < 4; ++jj) {
                float2 ha = unpack2(h2[2*jj]);
                float2 hb = unpack2(h2[2*jj+1]);
                int j0 = chunk * 16 + 4 * jj;
                const ulonglong2* w10 = reinterpret_cast<const ulonglong2*>(s_w1 + ((j0+0) << 4));
                const ulonglong2* w11 = reinterpret_cast<const ulonglong2*>(s_w1 + ((j0+1) << 4));
                const ulonglong2* w12 = reinterpret_cast<const ulonglong2*>(s_w1 + ((j0+2) << 4));
                const ulonglong2* w13 = reinterpret_cast<const ulonglong2*>(s_w1 + ((j0+3) << 4));
                u64 d0 = pack2dup(fmaxf(ha.x, 0.f));
                u64 d1 = pack2dup(fmaxf(ha.y, 0.f));
                u64 d2 = pack2dup(fmaxf(hb.x, 0.f));
                u64 d3 = pack2dup(fmaxf(hb.y, 0.f));
#pragma unroll
                for (int q = 0; q < 4; ++q) {
                    ulonglong2 t = w10[q];
                    ffma2(dx2[2*q],   d0, t.x);
                    ffma2(dx2[2*q+1], d0, t.y);
                }
#pragma unroll
                for (int q = 0; q < 4; ++q) {
                    ulonglong2 t = w11[q];
                    ffma2(dx2[2*q],   d1, t.x);
                    ffma2(dx2[2*q+1], d1, t.y);
                }
#pragma unroll
                for (int q = 0; q < 4; ++q) {
                    ulonglong2 t = w12[q];
                    ffma2(dx2[2*q],   d2, t.x);
                    ffma2(dx2[2*q+1], d2, t.y);
                }
#pragma unroll
                for (int q = 0; q < 4; ++q) {
                    ulonglong2 t = w13[q];
                    ffma2(dx2[2*q],   d3, t.x);
                    ffma2(dx2[2*q+1], d3, t.y);
                }
            }
        }

        // ---- residual update; channels 0..2 pinned ----
        float outv[CCH];
#pragma unroll
        for (int k = 0; k < 8; ++k) {
            float2 d = unpack2(dx2[k]);
            outv[2*k]   = perc[2*k]   + d.x;
            outv[2*k+1] = perc[2*k+1] + d.y;
        }
        outv[0] = perc[0]; outv[1] = perc[1]; outv[2] = perc[2];

        float4* dst = reinterpret_cast<float4*>(nxt + ((size_t)p << 4));
        dst[0] = make_float4(outv[0],  outv[1],  outv[2],  outv[3]);
        dst[1] = make_float4(outv[4],  outv[5],  outv[6],  outv[7]);
        dst[2] = make_float4(outv[8],  outv[9],  outv[10], outv[11]);
        dst[3] = make_float4(outv[12], outv[13], outv[14], outv[15]);
    }
}

// ---------------------------------------------------------------------------
// Unpack
// ---------------------------------------------------------------------------
__global__ void nca_unpack_kernel(float* __restrict__ out)
{
    int p = blockIdx.x * 256 + threadIdx.x;
    if (p >= NPIX) return;
    int b  = p >> 16;
    int hw = p & 65535;
    const float4* src = reinterpret_cast<const float4*>(g_state[0] + ((size_t)p << 4));
    float4 a0 = src[0], a1 = src[1], a2 = src[2], a3 = src[3];
    float v[CCH] = {a0.x,a0.y,a0.z,a0.w, a1.x,a1.y,a1.z,a1.w,
                    a2.x,a2.y,a2.z,a2.w, a3.x,a3.y,a3.z,a3.w};
    out[((size_t)b << 16) + hw] = v[3];
    float* xf = out + NPIX;
#pragma unroll
    for (int c = 0; c < CCH; ++c)
        xf[((size_t)(b * CCH + c) << 16) + hw] = v[c];
}

// ---------------------------------------------------------------------------
// Launch
// ---------------------------------------------------------------------------
extern "C" void kernel_launch(void* const* d_in, const int* in_sizes, int n_in,
                              void* d_out, int out_size)
{
    const float* x      = (const float*)d_in[0];
    const float* w_p0   = (const float*)d_in[1];
    const float* w_p1   = (const float*)d_in[2];
    const float* w_fc0  = (const float*)d_in[3];
    const float* b_fc0  = (const float*)d_in[4];
    const float* w_fc1  = (const float*)d_in[5];
    float* out = (float*)d_out;

    KeyArr keys;
    for (int j = 0; j < STEPS; ++j) {
        uint32_t a, b;
        threefry2x32(0u, 42u, 0u, (uint32_t)j, a, b);
        keys.k0[j] = a; keys.k1[j] = b;
    }

    cudaFuncSetAttribute(nca_step_kernel,
                         cudaFuncAttributeMaxDynamicSharedMemorySize, SMEM_BYTES);

    nca_pack_kernel<<<NPIX / 256, 256>>>(x);
    nca_maskall_kernel<<<NPIX / 256, 256>>>(keys);
    for (int s = 0; s < STEPS; ++s) {
        nca_step_kernel<<<TOT_BLOCKS, 256, SMEM_BYTES>>>(
            s & 1, s, w_p0, w_p1, w_fc0, b_fc0, w_fc1);
    }
    nca_unpack_kernel<<<NPIX / 256, 256>>>(out);
}

// round 8
// speedup vs baseline: 11.6669x; 2.1930x over previous
#include <cuda_runtime.h>
#include <cstdint>

// ---------------------------------------------------------------------------
// Problem constants
// ---------------------------------------------------------------------------
#define BATCH 8
#define IMG   256
#define CCH   16
#define HID   128
#define NPIX  (BATCH * IMG * IMG)          // 524288 pixels
#define STATE_ELEMS (NPIX * CCH)
#define STEPS 32
#define LIST_CAP (NPIX / 2 + 8192)

typedef unsigned long long u64;

__device__ float g_state[2][STATE_ELEMS];
__device__ int g_list[STEPS][LIST_CAP];
__device__ int g_ilist[STEPS][LIST_CAP];
__device__ int g_cnt[STEPS];
__device__ int g_icnt[STEPS];

struct KeyArr { uint32_t k0[STEPS]; uint32_t k1[STEPS]; };

// ---------------------------------------------------------------------------
// packed f32x2 helpers (bit-exact: two independent rn fp32 FMAs)
// ---------------------------------------------------------------------------
static __device__ __forceinline__ u64 pack2dup(float x) {
    u64 r; asm("mov.b64 %0, {%1, %1};" : "=l"(r) : "f"(x)); return r;
}
static __device__ __forceinline__ void ffma2(u64& acc, u64 a, u64 b) {
    asm("fma.rn.f32x2 %0, %1, %2, %0;" : "+l"(acc) : "l"(a), "l"(b));
}
static __device__ __forceinline__ float2 unpack2(u64 v) {
    float2 f; asm("mov.b64 {%0, %1}, %2;" : "=f"(f.x), "=f"(f.y) : "l"(v)); return f;
}

// ---------------------------------------------------------------------------
// Threefry-2x32 (20 rounds) — exact JAX implementation
// ---------------------------------------------------------------------------
static __host__ __device__ __forceinline__ uint32_t tf_rotl(uint32_t v, int r) {
    return (v << r) | (v >> (32 - r));
}
static __host__ __device__ __forceinline__ void threefry2x32(
    uint32_t k0, uint32_t k1, uint32_t x0, uint32_t x1,
    uint32_t& o0, uint32_t& o1)
{
    uint32_t ks2 = k0 ^ k1 ^ 0x1BD11BDAu;
    x0 += k0; x1 += k1;
    x0 += x1; x1 = tf_rotl(x1, 13); x1 ^= x0;
    x0 += x1; x1 = tf_rotl(x1, 15); x1 ^= x0;
    x0 += x1; x1 = tf_rotl(x1, 26); x1 ^= x0;
    x0 += x1; x1 = tf_rotl(x1,  6); x1 ^= x0;
    x0 += k1; x1 += ks2 + 1u;
    x0 += x1; x1 = tf_rotl(x1, 17); x1 ^= x0;
    x0 += x1; x1 = tf_rotl(x1, 29); x1 ^= x0;
    x0 += x1; x1 = tf_rotl(x1, 16); x1 ^= x0;
    x0 += x1; x1 = tf_rotl(x1, 24); x1 ^= x0;
    x0 += ks2; x1 += k0 + 2u;
    x0 += x1; x1 = tf_rotl(x1, 13); x1 ^= x0;
    x0 += x1; x1 = tf_rotl(x1, 15); x1 ^= x0;
    x0 += x1; x1 = tf_rotl(x1, 26); x1 ^= x0;
    x0 += x1; x1 = tf_rotl(x1,  6); x1 ^= x0;
    x0 += k0; x1 += k1 + 3u;
    x0 += x1; x1 = tf_rotl(x1, 17); x1 ^= x0;
    x0 += x1; x1 = tf_rotl(x1, 29); x1 ^= x0;
    x0 += x1; x1 = tf_rotl(x1, 16); x1 ^= x0;
    x0 += x1; x1 = tf_rotl(x1, 24); x1 ^= x0;
    x0 += k1; x1 += ks2 + 4u;
    x0 += x1; x1 = tf_rotl(x1, 13); x1 ^= x0;
    x0 += x1; x1 = tf_rotl(x1, 15); x1 ^= x0;
    x0 += x1; x1 = tf_rotl(x1, 26); x1 ^= x0;
    x0 += x1; x1 = tf_rotl(x1,  6); x1 ^= x0;
    x0 += ks2; x1 += k0 + 5u;
    o0 = x0; o1 = x1;
}

// ---------------------------------------------------------------------------
// Pack: NCHW -> NHWC state 0; zero list counters
// ---------------------------------------------------------------------------
__global__ void nca_pack_kernel(const float* __restrict__ x)
{
    int p = blockIdx.x * 256 + threadIdx.x;
    if (blockIdx.x == 0 && threadIdx.x < STEPS) {
        g_cnt[threadIdx.x] = 0;
        g_icnt[threadIdx.x] = 0;
    }
    if (p >= NPIX) return;
    int b  = p >> 16;
    int hw = p & 65535;
    float v[CCH];
#pragma unroll
    for (int c = 0; c < CCH; ++c)
        v[c] = x[((size_t)(b * CCH + c) << 16) + hw];
    float4* dst = reinterpret_cast<float4*>(g_state[0] + ((size_t)p << 4));
    dst[0] = make_float4(v[0],  v[1],  v[2],  v[3]);
    dst[1] = make_float4(v[4],  v[5],  v[6],  v[7]);
    dst[2] = make_float4(v[8],  v[9],  v[10], v[11]);
    dst[3] = make_float4(v[12], v[13], v[14], v[15]);
}

// ---------------------------------------------------------------------------
// All 32 fire masks in one pass
// ---------------------------------------------------------------------------
__global__ void nca_maskall_kernel(KeyArr keys)
{
    int p = blockIdx.x * 256 + threadIdx.x;
    const int lane = threadIdx.x & 31;

#pragma unroll 1
    for (int s = 0; s < STEPS; ++s) {
        uint32_t r0, r1;
        threefry2x32(keys.k0[s], keys.k1[s], 0u, (uint32_t)p, r0, r1);
        uint32_t bits = r0 ^ r1;
        float u = __uint_as_float((bits >> 9) | 0x3f800000u) - 1.0f;
        bool active = (u <= 0.5f);

        unsigned ball = __ballot_sync(0xffffffffu, active);
        int nact = __popc(ball);
        int rank = __popc(ball & ((1u << lane) - 1u));
        int baseA = 0, baseI = 0;
        if (lane == 0) {
            if (nact > 0)  baseA = atomicAdd(&g_cnt[s], nact);
            if (nact < 32) baseI = atomicAdd(&g_icnt[s], 32 - nact);
        }
        baseA = __shfl_sync(0xffffffffu, baseA, 0);
        baseI = __shfl_sync(0xffffffffu, baseI, 0);
        if (active) g_list[s][baseA + rank] = p;
        else        g_ilist[s][baseI + (lane - rank)] = p;
    }
}

// ---------------------------------------------------------------------------
// Per-step fused kernel: active MLP blocks + inactive copy blocks
// (R5 structure; min-blocks-per-SM = 3 to force regs <= 168 -> 12 warps/SM)
// ---------------------------------------------------------------------------
#define SMEM_FLOATS (6144 + 2048 + 128 + 144 + 144)
#define SMEM_BYTES  (SMEM_FLOATS * 4)
#define UPD_BLOCKS  512
#define CPY_BLOCKS  256
#define TOT_BLOCKS  (UPD_BLOCKS + CPY_BLOCKS)

__global__ void __launch_bounds__(128, 3)
nca_step_kernel(int src, int step,
                const float* __restrict__ w_p0, const float* __restrict__ w_p1,
                const float* __restrict__ w_fc0, const float* __restrict__ b_fc0,
                const float* __restrict__ w_fc1)
{
    const float* cur = g_state[src];
    float*       nxt = g_state[src ^ 1];
    const int tid = threadIdx.x;

    // ---------------- inactive copy-through blocks ----------------
    if (blockIdx.x >= UPD_BLOCKS) {
        const int icnt = g_icnt[step];
        const int* il = g_ilist[step];
        for (int i = (blockIdx.x - UPD_BLOCKS) * 128 + tid; i < icnt;
             i += CPY_BLOCKS * 128) {
            int p = il[i];
            const float4* s = reinterpret_cast<const float4*>(cur + ((size_t)p << 4));
            float4* d = reinterpret_cast<float4*>(nxt + ((size_t)p << 4));
            d[0] = s[0]; d[1] = s[1]; d[2] = s[2]; d[3] = s[3];
        }
        return;
    }

    // ---------------- active MLP blocks ----------------
    extern __shared__ float sm[];
    float* s_w0 = sm;            // 6144
    float* s_w1 = sm + 6144;     // 2048
    float* s_b  = sm + 8192;     // 128
    float* s_p0 = sm + 8320;     // 144
    float* s_p1 = sm + 8464;     // 144

    for (int i = tid; i < 6144; i += 128) s_w0[i] = w_fc0[i];
    for (int i = tid; i < 2048; i += 128) s_w1[i] = w_fc1[i];
    s_b[tid] = b_fc0[tid];
    for (int i = tid; i < 144; i += 128) { s_p0[i] = w_p0[i]; s_p1[i] = w_p1[i]; }
    __syncthreads();

    const int count = g_cnt[step];
    const int* al = g_list[step];

#pragma unroll 1
    for (int base = blockIdx.x * 256; base < count; base += UPD_BLOCKS * 256) {
        int iA = base + tid;
        if (iA >= count) continue;
        int iB = base + 128 + tid;
        int pA = al[iA];
        int pB = (iB < count) ? al[iB] : pA;   // duplicate is benign

        const float* baseA = cur + ((size_t)(pA >> 16) << 20);
        const float* baseB = cur + ((size_t)(pB >> 16) << 20);
        const int hA = (pA >> 8) & 255, wA = pA & 255;
        const int hB = (pB >> 8) & 255, wB = pB & 255;

        // ---- perception for BOTH pixels, tap-outer (shared tap weights) ----
        float percA[48], percB[48];
        {
            u64 cA0[8], cA1[8], cB0[8], cB1[8];
#pragma unroll
            for (int k = 0; k < 8; ++k) { cA0[k]=0ull; cA1[k]=0ull; cB0[k]=0ull; cB1[k]=0ull; }

#pragma unroll
            for (int dh = -1; dh <= 1; ++dh) {
                int hhA = hA + dh; hhA = (hhA < 0) ? 1 : ((hhA > 255) ? 254 : hhA);
                int hhB = hB + dh; hhB = (hhB < 0) ? 1 : ((hhB > 255) ? 254 : hhB);
#pragma unroll
                for (int dw = -1; dw <= 1; ++dw) {
                    int wwA = wA + dw; wwA = (wwA < 0) ? 1 : ((wwA > 255) ? 254 : wwA);
                    int wwB = wB + dw; wwB = (wwB < 0) ? 1 : ((wwB > 255) ? 254 : wwB);
                    const ulonglong2* pxA = reinterpret_cast<const ulonglong2*>(
                        baseA + (((size_t)((hhA << 8) | wwA)) << 4));
                    const ulonglong2* pxB = reinterpret_cast<const ulonglong2*>(
                        baseB + (((size_t)((hhB << 8) | wwB)) << 4));
                    ulonglong2 qa0 = pxA[0], qa1 = pxA[1], qa2 = pxA[2], qa3 = pxA[3];
                    ulonglong2 qb0 = pxB[0], qb1 = pxB[1], qb2 = pxB[2], qb3 = pxB[3];
                    u64 va[8] = {qa0.x,qa0.y,qa1.x,qa1.y,qa2.x,qa2.y,qa3.x,qa3.y};
                    u64 vb[8] = {qb0.x,qb0.y,qb1.x,qb1.y,qb2.x,qb2.y,qb3.x,qb3.y};
                    const int tap = (dh + 1) * 3 + (dw + 1);
                    const ulonglong2* wp0 = reinterpret_cast<const ulonglong2*>(s_p0 + tap * 16);
                    const ulonglong2* wp1 = reinterpret_cast<const ulonglong2*>(s_p1 + tap * 16);
#pragma unroll
                    for (int q = 0; q < 4; ++q) {
                        ulonglong2 t0 = wp0[q], t1 = wp1[q];
                        ffma2(cA0[2*q],   va[2*q],   t0.x);
                        ffma2(cA0[2*q+1], va[2*q+1], t0.y);
                        ffma2(cA1[2*q],   va[2*q],   t1.x);
                        ffma2(cA1[2*q+1], va[2*q+1], t1.y);
                        ffma2(cB0[2*q],   vb[2*q],   t0.x);
                        ffma2(cB0[2*q+1], vb[2*q+1], t0.y);
                        ffma2(cB1[2*q],   vb[2*q],   t1.x);
                        ffma2(cB1[2*q+1], vb[2*q+1], t1.y);
                    }
                    if (dh == 0 && dw == 0) {
#pragma unroll
                        for (int q = 0; q < 8; ++q) {
                            float2 fa = unpack2(va[q]);
                            float2 fb = unpack2(vb[q]);
                            percA[2*q] = fa.x; percA[2*q+1] = fa.y;
                            percB[2*q] = fb.x; percB[2*q+1] = fb.y;
                        }
                    }
                }
            }
#pragma unroll
            for (int k = 0; k < 8; ++k) {
                float2 a0 = unpack2(cA0[k]);
                float2 a1 = unpack2(cA1[k]);
                float2 b0 = unpack2(cB0[k]);
                float2 b1 = unpack2(cB1[k]);
                percA[16 + 2*k] = a0.x; percA[16 + 2*k + 1] = a0.y;
                percA[32 + 2*k] = a1.x; percA[32 + 2*k + 1] = a1.y;
                percB[16 + 2*k] = b0.x; percB[16 + 2*k + 1] = b0.y;
                percB[32 + 2*k] = b1.x; percB[32 + 2*k + 1] = b1.y;
            }
        }

        // ---- fused MLP: 8 chunks of 16 hidden units, 2 pixels ----
        u64 dxA[8], dxB[8];
#pragma unroll
        for (int k = 0; k < 8; ++k) { dxA[k] = 0ull; dxB[k] = 0ull; }

#pragma unroll 1
        for (int chunk = 0; chunk < 8; ++chunk) {
            u64 hA2[8], hB2[8];
            {
                const ulonglong2* bv = reinterpret_cast<const ulonglong2*>(s_b + chunk * 16);
#pragma unroll
                for (int q = 0; q < 4; ++q) {
                    ulonglong2 t = bv[q];
                    hA2[2*q] = t.x; hA2[2*q+1] = t.y;
                    hB2[2*q] = t.x; hB2[2*q+1] = t.y;
                }
            }
#pragma unroll
            for (int c = 0; c < 48; ++c) {
                u64 pa2 = pack2dup(percA[c]);
                u64 pb2 = pack2dup(percB[c]);
                const ulonglong2* wr = reinterpret_cast<const ulonglong2*>(
                    s_w0 + c * HID + chunk * 16);
#pragma unroll
                for (int q = 0; q < 4; ++q) {
                    ulonglong2 t = wr[q];
                    ffma2(hA2[2*q],   pa2, t.x);
                    ffma2(hA2[2*q+1], pa2, t.y);
                    ffma2(hB2[2*q],   pb2, t.x);
                    ffma2(hB2[2*q+1], pb2, t.y);
                }
            }
            // relu + second layer
#pragma unroll
            for (int jj = 0; jj < 4; ++jj) {
                float2 ha = unpack2(hA2[2*jj]);
                float2 ha2 = unpack2(hA2[2*jj+1]);
                float2 hb = unpack2(hB2[2*jj]);
                float2 hb2 = unpack2(hB2[2*jj+1]);
                int j0 = chunk * 16 + 4 * jj;
                const ulonglong2* w10 = reinterpret_cast<const ulonglong2*>(s_w1 + ((j0+0) << 4));
                const ulonglong2* w11 = reinterpret_cast<const ulonglong2*>(s_w1 + ((j0+1) << 4));
                const ulonglong2* w12 = reinterpret_cast<const ulonglong2*>(s_w1 + ((j0+2) << 4));
                const ulonglong2* w13 = reinterpret_cast<const ulonglong2*>(s_w1 + ((j0+3) << 4));
                u64 dA0 = pack2dup(fmaxf(ha.x,  0.f));
                u64 dA1 = pack2dup(fmaxf(ha.y,  0.f));
                u64 dA2 = pack2dup(fmaxf(ha2.x, 0.f));
                u64 dA3 = pack2dup(fmaxf(ha2.y, 0.f));
                u64 dB0 = pack2dup(fmaxf(hb.x,  0.f));
                u64 dB1 = pack2dup(fmaxf(hb.y,  0.f));
                u64 dB2 = pack2dup(fmaxf(hb2.x, 0.f));
                u64 dB3 = pack2dup(fmaxf(hb2.y, 0.f));
#pragma unroll
                for (int q = 0; q < 4; ++q) {
                    ulonglong2 t0 = w10[q];
                    ffma2(dxA[2*q],   dA0, t0.x);
                    ffma2(dxA[2*q+1], dA0, t0.y);
                    ffma2(dxB[2*q],   dB0, t0.x);
                    ffma2(dxB[2*q+1], dB0, t0.y);
                }
#pragma unroll
                for (int q = 0; q < 4; ++q) {
                    ulonglong2 t1 = w11[q];
                    ffma2(dxA[2*q],   dA1, t1.x);
                    ffma2(dxA[2*q+1], dA1, t1.y);
                    ffma2(dxB[2*q],   dB1, t1.x);
                    ffma2(dxB[2*q+1], dB1, t1.y);
                }
#pragma unroll
                for (int q = 0; q < 4; ++q) {
                    ulonglong2 t2 = w12[q];
                    ffma2(dxA[2*q],   dA2, t2.x);
                    ffma2(dxA[2*q+1], dA2, t2.y);
                    ffma2(dxB[2*q],   dB2, t2.x);
                    ffma2(dxB[2*q+1], dB2, t2.y);
                }
#pragma unroll
                for (int q = 0; q < 4; ++q) {
                    ulonglong2 t3 = w13[q];
                    ffma2(dxA[2*q],   dA3, t3.x);
                    ffma2(dxA[2*q+1], dA3, t3.y);
                    ffma2(dxB[2*q],   dB3, t3.x);
                    ffma2(dxB[2*q+1], dB3, t3.y);
                }
            }
        }

        // ---- residual update; channels 0..2 pinned ----
        float outA[CCH], outB[CCH];
#pragma unroll
        for (int k = 0; k < 8; ++k) {
            float2 da = unpack2(dxA[k]);
            float2 db = unpack2(dxB[k]);
            outA[2*k]   = percA[2*k]   + da.x;
            outA[2*k+1] = percA[2*k+1] + da.y;
            outB[2*k]   = percB[2*k]   + db.x;
            outB[2*k+1] = percB[2*k+1] + db.y;
        }
        outA[0] = percA[0]; outA[1] = percA[1]; outA[2] = percA[2];
        outB[0] = percB[0]; outB[1] = percB[1]; outB[2] = percB[2];

        float4* dA = reinterpret_cast<float4*>(nxt + ((size_t)pA << 4));
        dA[0] = make_float4(outA[0],  outA[1],  outA[2],  outA[3]);
        dA[1] = make_float4(outA[4],  outA[5],  outA[6],  outA[7]);
        dA[2] = make_float4(outA[8],  outA[9],  outA[10], outA[11]);
        dA[3] = make_float4(outA[12], outA[13], outA[14], outA[15]);
        float4* dB = reinterpret_cast<float4*>(nxt + ((size_t)pB << 4));
        dB[0] = make_float4(outB[0],  outB[1],  outB[2],  outB[3]);
        dB[1] = make_float4(outB[4],  outB[5],  outB[6],  outB[7]);
        dB[2] = make_float4(outB[8],  outB[9],  outB[10], outB[11]);
        dB[3] = make_float4(outB[12], outB[13], outB[14], outB[15]);
    }
}

// ---------------------------------------------------------------------------
// Unpack
// ---------------------------------------------------------------------------
__global__ void nca_unpack_kernel(float* __restrict__ out)
{
    int p = blockIdx.x * 256 + threadIdx.x;
    if (p >= NPIX) return;
    int b  = p >> 16;
    int hw = p & 65535;
    const float4* src = reinterpret_cast<const float4*>(g_state[0] + ((size_t)p << 4));
    float4 a0 = src[0], a1 = src[1], a2 = src[2], a3 = src[3];
    float v[CCH] = {a0.x,a0.y,a0.z,a0.w, a1.x,a1.y,a1.z,a1.w,
                    a2.x,a2.y,a2.z,a2.w, a3.x,a3.y,a3.z,a3.w};
    out[((size_t)b << 16) + hw] = v[3];
    float* xf = out + NPIX;
#pragma unroll
    for (int c = 0; c < CCH; ++c)
        xf[((size_t)(b * CCH + c) << 16) + hw] = v[c];
}

// ---------------------------------------------------------------------------
// Launch
// ---------------------------------------------------------------------------
extern "C" void kernel_launch(void* const* d_in, const int* in_sizes, int n_in,
                              void* d_out, int out_size)
{
    const float* x      = (const float*)d_in[0];
    const float* w_p0   = (const float*)d_in[1];
    const float* w_p1   = (const float*)d_in[2];
    const float* w_fc0  = (const float*)d_in[3];
    const float* b_fc0  = (const float*)d_in[4];
    const float* w_fc1  = (const float*)d_in[5];
    float* out = (float*)d_out;

    KeyArr keys;
    for (int j = 0; j < STEPS; ++j) {
        uint32_t a, b;
        threefry2x32(0u, 42u, 0u, (uint32_t)j, a, b);
        keys.k0[j] = a; keys.k1[j] = b;
    }

    cudaFuncSetAttribute(nca_step_kernel,
                         cudaFuncAttributeMaxDynamicSharedMemorySize, SMEM_BYTES);

    nca_pack_kernel<<<NPIX / 256, 256>>>(x);
    nca_maskall_kernel<<<NPIX / 256, 256>>>(keys);
    for (int s = 0; s < STEPS; ++s) {
        nca_step_kernel<<<TOT_BLOCKS, 128, SMEM_BYTES>>>(
            s & 1, s, w_p0, w_p1, w_fc0, b_fc0, w_fc1);
    }
    nca_unpack_kernel<<<NPIX / 256, 256>>>(out);
}

// round 10
// speedup vs baseline: 13.0073x; 1.1149x over previous
#include <cuda_runtime.h>
#include <cstdint>

// ---------------------------------------------------------------------------
// Problem constants
// ---------------------------------------------------------------------------
#define BATCH 8
#define IMG   256
#define CCH   16
#define HID   128
#define NPIX  (BATCH * IMG * IMG)
#define STATE_ELEMS (NPIX * CCH)
#define STEPS 32
#define LIST_CAP (NPIX / 2 + 8192)
#define NSM_BLOCKS 148

typedef unsigned long long u64;

__device__ float g_state[2][STATE_ELEMS];
__device__ int g_list[STEPS][LIST_CAP];
__device__ int g_ilist[STEPS][LIST_CAP];
__device__ int g_cnt[STEPS];
__device__ int g_icnt[STEPS];
// W0^T split into tf32 hi/lo: [n=128][k=48]
__device__ float g_w0t_hi[HID * 48];
__device__ float g_w0t_lo[HID * 48];

struct KeyArr { uint32_t k0[STEPS]; uint32_t k1[STEPS]; };

// ---------------------------------------------------------------------------
// packed f32x2 helpers (bit-exact: two independent rn fp32 FMAs)
// ---------------------------------------------------------------------------
static __device__ __forceinline__ u64 pack2dup(float x) {
    u64 r; asm("mov.b64 %0, {%1, %1};" : "=l"(r) : "f"(x)); return r;
}
static __device__ __forceinline__ void ffma2(u64& acc, u64 a, u64 b) {
    asm("fma.rn.f32x2 %0, %1, %2, %0;" : "+l"(acc) : "l"(a), "l"(b));
}
static __device__ __forceinline__ float2 unpack2(u64 v) {
    float2 f; asm("mov.b64 {%0, %1}, %2;" : "=f"(f.x), "=f"(f.y) : "l"(v)); return f;
}

// ---------------------------------------------------------------------------
// tf32 split
// ---------------------------------------------------------------------------
static __device__ __forceinline__ uint32_t cvt_tf32(float v) {
    uint32_t r; asm("cvt.rna.tf32.f32 %0, %1;" : "=r"(r) : "f"(v)); return r;
}
static __device__ __forceinline__ void split_tf32(float v, uint32_t& hi, uint32_t& lo) {
    hi = cvt_tf32(v);
    lo = cvt_tf32(v - __uint_as_float(hi));
}

// ---------------------------------------------------------------------------
// warp mma: m16n8k8 tf32 (sm_80 baseline PTX — legal on sm_103)
// ---------------------------------------------------------------------------
static __device__ __forceinline__ void mma_tf32(
    float* d, const uint32_t* a, uint32_t b0, uint32_t b1)
{
    asm volatile(
        "mma.sync.aligned.m16n8k8.row.col.f32.tf32.tf32.f32 "
        "{%0,%1,%2,%3},{%4,%5,%6,%7},{%8,%9},{%0,%1,%2,%3};"
        : "+f"(d[0]), "+f"(d[1]), "+f"(d[2]), "+f"(d[3])
        : "r"(a[0]), "r"(a[1]), "r"(a[2]), "r"(a[3]), "r"(b0), "r"(b1));
}

// ---------------------------------------------------------------------------
// Threefry-2x32 — exact JAX
// ---------------------------------------------------------------------------
static __host__ __device__ __forceinline__ uint32_t tf_rotl(uint32_t v, int r) {
    return (v << r) | (v >> (32 - r));
}
static __host__ __device__ __forceinline__ void threefry2x32(
    uint32_t k0, uint32_t k1, uint32_t x0, uint32_t x1,
    uint32_t& o0, uint32_t& o1)
{
    uint32_t ks2 = k0 ^ k1 ^ 0x1BD11BDAu;
    x0 += k0; x1 += k1;
    x0 += x1; x1 = tf_rotl(x1, 13); x1 ^= x0;
    x0 += x1; x1 = tf_rotl(x1, 15); x1 ^= x0;
    x0 += x1; x1 = tf_rotl(x1, 26); x1 ^= x0;
    x0 += x1; x1 = tf_rotl(x1,  6); x1 ^= x0;
    x0 += k1; x1 += ks2 + 1u;
    x0 += x1; x1 = tf_rotl(x1, 17); x1 ^= x0;
    x0 += x1; x1 = tf_rotl(x1, 29); x1 ^= x0;
    x0 += x1; x1 = tf_rotl(x1, 16); x1 ^= x0;
    x0 += x1; x1 = tf_rotl(x1, 24); x1 ^= x0;
    x0 += ks2; x1 += k0 + 2u;
    x0 += x1; x1 = tf_rotl(x1, 13); x1 ^= x0;
    x0 += x1; x1 = tf_rotl(x1, 15); x1 ^= x0;
    x0 += x1; x1 = tf_rotl(x1, 26); x1 ^= x0;
    x0 += x1; x1 = tf_rotl(x1,  6); x1 ^= x0;
    x0 += k0; x1 += k1 + 3u;
    x0 += x1; x1 = tf_rotl(x1, 17); x1 ^= x0;
    x0 += x1; x1 = tf_rotl(x1, 29); x1 ^= x0;
    x0 += x1; x1 = tf_rotl(x1, 16); x1 ^= x0;
    x0 += x1; x1 = tf_rotl(x1, 24); x1 ^= x0;
    x0 += k1; x1 += ks2 + 4u;
    x0 += x1; x1 = tf_rotl(x1, 13); x1 ^= x0;
    x0 += x1; x1 = tf_rotl(x1, 15); x1 ^= x0;
    x0 += x1; x1 = tf_rotl(x1, 26); x1 ^= x0;
    x0 += x1; x1 = tf_rotl(x1,  6); x1 ^= x0;
    x0 += ks2; x1 += k0 + 5u;
    o0 = x0; o1 = x1;
}

// ---------------------------------------------------------------------------
// Pack / maskall / prep / unpack
// ---------------------------------------------------------------------------
__global__ void nca_pack_kernel(const float* __restrict__ x)
{
    int p = blockIdx.x * 256 + threadIdx.x;
    if (blockIdx.x == 0 && threadIdx.x < STEPS) {
        g_cnt[threadIdx.x] = 0; g_icnt[threadIdx.x] = 0;
    }
    if (p >= NPIX) return;
    int b = p >> 16, hw = p & 65535;
    float v[CCH];
#pragma unroll
    for (int c = 0; c < CCH; ++c)
        v[c] = x[((size_t)(b * CCH + c) << 16) + hw];
    float4* dst = reinterpret_cast<float4*>(g_state[0] + ((size_t)p << 4));
    dst[0] = make_float4(v[0], v[1], v[2], v[3]);
    dst[1] = make_float4(v[4], v[5], v[6], v[7]);
    dst[2] = make_float4(v[8], v[9], v[10], v[11]);
    dst[3] = make_float4(v[12], v[13], v[14], v[15]);
}

__global__ void nca_maskall_kernel(KeyArr keys)
{
    int p = blockIdx.x * 256 + threadIdx.x;
    const int lane = threadIdx.x & 31;
#pragma unroll 1
    for (int s = 0; s < STEPS; ++s) {
        uint32_t r0, r1;
        threefry2x32(keys.k0[s], keys.k1[s], 0u, (uint32_t)p, r0, r1);
        uint32_t bits = r0 ^ r1;
        float u = __uint_as_float((bits >> 9) | 0x3f800000u) - 1.0f;
        bool active = (u <= 0.5f);
        unsigned ball = __ballot_sync(0xffffffffu, active);
        int nact = __popc(ball);
        int rank = __popc(ball & ((1u << lane) - 1u));
        int baseA = 0, baseI = 0;
        if (lane == 0) {
            if (nact > 0)  baseA = atomicAdd(&g_cnt[s], nact);
            if (nact < 32) baseI = atomicAdd(&g_icnt[s], 32 - nact);
        }
        baseA = __shfl_sync(0xffffffffu, baseA, 0);
        baseI = __shfl_sync(0xffffffffu, baseI, 0);
        if (active) g_list[s][baseA + rank] = p;
        else        g_ilist[s][baseI + (lane - rank)] = p;
    }
}

__global__ void nca_prep_kernel(const float* __restrict__ w_fc0)
{
    int i = blockIdx.x * 256 + threadIdx.x;
    if (i < HID * 48) {
        int n = i / 48, k = i % 48;
        uint32_t hi, lo; split_tf32(w_fc0[k * HID + n], hi, lo);
        g_w0t_hi[i] = __uint_as_float(hi);
        g_w0t_lo[i] = __uint_as_float(lo);
    }
}

__global__ void nca_unpack_kernel(float* __restrict__ out)
{
    int p = blockIdx.x * 256 + threadIdx.x;
    if (p >= NPIX) return;
    int b = p >> 16, hw = p & 65535;
    const float4* src = reinterpret_cast<const float4*>(g_state[0] + ((size_t)p << 4));
    float4 a0 = src[0], a1 = src[1], a2 = src[2], a3 = src[3];
    float v[CCH] = {a0.x,a0.y,a0.z,a0.w, a1.x,a1.y,a1.z,a1.w,
                    a2.x,a2.y,a2.z,a2.w, a3.x,a3.y,a3.z,a3.w};
    out[((size_t)b << 16) + hw] = v[3];
    float* xf = out + NPIX;
#pragma unroll
    for (int c = 0; c < CCH; ++c)
        xf[((size_t)(b * CCH + c) << 16) + hw] = v[c];
}

// ---------------------------------------------------------------------------
// SMEM layout (float offsets); rows padded for conflict-free fragment access
// ---------------------------------------------------------------------------
#define AP 52      // A/B row pad (48 data floats)
#define W1P 20
#define SM_BIAS 0                       // 128
#define SM_P0   128                     // 144
#define SM_P1   272                     // 144
#define SM_W1   416                     // 128*20 = 2560
#define SM_BH   (SM_W1 + 2560)          // 128*52 = 6656
#define SM_BL   (SM_BH + 6656)          // 6656
#define SM_AH   (SM_BL + 6656)          // 256*52 = 13312
#define SM_AL   (SM_AH + 13312)         // 13312
#define SM_DX   (SM_AL + 13312)         // 256*20 = 5120
#define SM_FLOATS (SM_DX + 5120)        // 48032 floats = 192128 B
#define SM_BYTES  (SM_FLOATS * 4)

// ---------------------------------------------------------------------------
// Step kernel: persistent 148 blocks x 256 threads; 256-px tiles
// ---------------------------------------------------------------------------
__global__ void __launch_bounds__(256, 1)
nca_step_mma(int src, int step,
             const float* __restrict__ w_p0, const float* __restrict__ w_p1,
             const float* __restrict__ b_fc0, const float* __restrict__ w_fc1)
{
    extern __shared__ float sm[];
    float* s_bias = sm + SM_BIAS;
    float* s_p0   = sm + SM_P0;
    float* s_p1   = sm + SM_P1;
    float* s_W1   = sm + SM_W1;
    float* s_BH   = sm + SM_BH;
    float* s_BL   = sm + SM_BL;
    float* s_AH   = sm + SM_AH;
    float* s_AL   = sm + SM_AL;
    float* s_DX   = sm + SM_DX;

    const float* cur = g_state[src];
    float*       nxt = g_state[src ^ 1];
    const int tid  = threadIdx.x;
    const int lane = tid & 31;
    const int g  = lane >> 2;
    const int tg = lane & 3;
    const int R  = (tid >> 5) * 32;   // warp's row base in the 256-row tile

    // ---- stage constants once ----
    if (tid < 128) s_bias[tid] = b_fc0[tid];
    if (tid < 144) { s_p0[tid] = w_p0[tid]; s_p1[tid] = w_p1[tid]; }
    for (int i = tid; i < HID * CCH; i += 256)
        s_W1[(i >> 4) * W1P + (i & 15)] = w_fc1[i];
    for (int i = tid; i < HID * 48; i += 256) {
        int n = i / 48, k = i % 48;
        s_BH[n * AP + k] = g_w0t_hi[i];
        s_BL[n * AP + k] = g_w0t_lo[i];
    }
    __syncthreads();

    const int count = g_cnt[step];
    const int* al = g_list[step];
    const int ntiles = (count + 255) >> 8;

#pragma unroll 1
    for (int tile = blockIdx.x; tile < ntiles; tile += NSM_BLOCKS) {
        const int i = tile * 256 + tid;
        const int p = al[(i < count) ? i : (count - 1)];
        const float* base = cur + ((size_t)(p >> 16) << 20);
        const int h = (p >> 8) & 255, w = p & 255;

        // ---- perception (bit-exact packed fp32x2) ----
        float perc[48];
        {
            u64 c0a[8], c1a[8];
#pragma unroll
            for (int k = 0; k < 8; ++k) { c0a[k] = 0ull; c1a[k] = 0ull; }
#pragma unroll
            for (int dh = -1; dh <= 1; ++dh) {
                int hh = h + dh; hh = (hh < 0) ? 1 : ((hh > 255) ? 254 : hh);
#pragma unroll
                for (int dw = -1; dw <= 1; ++dw) {
                    int ww = w + dw; ww = (ww < 0) ? 1 : ((ww > 255) ? 254 : ww);
                    const ulonglong2* px = reinterpret_cast<const ulonglong2*>(
                        base + (((size_t)((hh << 8) | ww)) << 4));
                    ulonglong2 q0 = px[0], q1 = px[1], q2 = px[2], q3 = px[3];
                    u64 vv[8] = {q0.x,q0.y,q1.x,q1.y,q2.x,q2.y,q3.x,q3.y};
                    const int tap = (dh + 1) * 3 + (dw + 1);
                    const ulonglong2* wp0 = reinterpret_cast<const ulonglong2*>(s_p0 + tap * 16);
                    const ulonglong2* wp1 = reinterpret_cast<const ulonglong2*>(s_p1 + tap * 16);
#pragma unroll
                    for (int q = 0; q < 4; ++q) {
                        ulonglong2 t0 = wp0[q], t1 = wp1[q];
                        ffma2(c0a[2*q],   vv[2*q],   t0.x);
                        ffma2(c0a[2*q+1], vv[2*q+1], t0.y);
                        ffma2(c1a[2*q],   vv[2*q],   t1.x);
                        ffma2(c1a[2*q+1], vv[2*q+1], t1.y);
                    }
                    if (dh == 0 && dw == 0) {
#pragma unroll
                        for (int q = 0; q < 8; ++q) {
                            float2 f = unpack2(vv[q]);
                            perc[2*q] = f.x; perc[2*q+1] = f.y;
                        }
                    }
                }
            }
#pragma unroll
            for (int k = 0; k < 8; ++k) {
                float2 a = unpack2(c0a[k]);
                float2 b = unpack2(c1a[k]);
                perc[16 + 2*k] = a.x; perc[16 + 2*k + 1] = a.y;
                perc[32 + 2*k] = b.x; perc[32 + 2*k + 1] = b.y;
            }
        }
        float cen[CCH];
#pragma unroll
        for (int c = 0; c < CCH; ++c) cen[c] = perc[c];

        // ---- split + store A row (row = tid) ----
#pragma unroll
        for (int g4 = 0; g4 < 12; ++g4) {
            uint32_t hi[4], lo[4];
#pragma unroll
            for (int j = 0; j < 4; ++j) split_tf32(perc[4*g4 + j], hi[j], lo[j]);
            float4 vh = make_float4(__uint_as_float(hi[0]), __uint_as_float(hi[1]),
                                    __uint_as_float(hi[2]), __uint_as_float(hi[3]));
            float4 vl = make_float4(__uint_as_float(lo[0]), __uint_as_float(lo[1]),
                                    __uint_as_float(lo[2]), __uint_as_float(lo[3]));
            *reinterpret_cast<float4*>(s_AH + tid * AP + 4*g4) = vh;
            *reinterpret_cast<float4*>(s_AL + tid * AP + 4*g4) = vl;
        }
        __syncwarp();

        // ---- GEMM1 (mma.sync tf32, 3-term split) + fused epilogue/GEMM2 ----
        u64 dx2[2][2][8];
#pragma unroll
        for (int m = 0; m < 2; ++m)
#pragma unroll
            for (int r = 0; r < 2; ++r)
#pragma unroll
                for (int j = 0; j < 8; ++j) dx2[m][r][j] = 0ull;

#pragma unroll 1
        for (int nh = 0; nh < 2; ++nh) {
            float acc[2][8][4];
#pragma unroll
            for (int m = 0; m < 2; ++m)
#pragma unroll
                for (int nt = 0; nt < 8; ++nt)
#pragma unroll
                    for (int j = 0; j < 4; ++j) acc[m][nt][j] = 0.0f;

#pragma unroll 1
            for (int kt = 0; kt < 6; ++kt) {
                const int kc = kt * 8 + tg;
                uint32_t ah[2][4], alr[2][4];
#pragma unroll
                for (int m = 0; m < 2; ++m) {
                    const int r0 = R + m * 16 + g;
                    ah[m][0]  = __float_as_uint(s_AH[r0 * AP + kc]);
                    ah[m][1]  = __float_as_uint(s_AH[(r0 + 8) * AP + kc]);
                    ah[m][2]  = __float_as_uint(s_AH[r0 * AP + kc + 4]);
                    ah[m][3]  = __float_as_uint(s_AH[(r0 + 8) * AP + kc + 4]);
                    alr[m][0] = __float_as_uint(s_AL[r0 * AP + kc]);
                    alr[m][1] = __float_as_uint(s_AL[(r0 + 8) * AP + kc]);
                    alr[m][2] = __float_as_uint(s_AL[r0 * AP + kc + 4]);
                    alr[m][3] = __float_as_uint(s_AL[(r0 + 8) * AP + kc + 4]);
                }
#pragma unroll
                for (int nt = 0; nt < 8; ++nt) {
                    const int n = (nh * 8 + nt) * 8 + g;
                    uint32_t bh0 = __float_as_uint(s_BH[n * AP + kc]);
                    uint32_t bh1 = __float_as_uint(s_BH[n * AP + kc + 4]);
                    uint32_t bl0 = __float_as_uint(s_BL[n * AP + kc]);
                    uint32_t bl1 = __float_as_uint(s_BL[n * AP + kc + 4]);
#pragma unroll
                    for (int m = 0; m < 2; ++m) {
                        mma_tf32(acc[m][nt], ah[m],  bh0, bh1);
                        mma_tf32(acc[m][nt], ah[m],  bl0, bl1);
                        mma_tf32(acc[m][nt], alr[m], bh0, bh1);
                    }
                }
            }

            // epilogue: bias + relu on D frags; GEMM2 partial (packed FFMA2)
#pragma unroll
            for (int nt = 0; nt < 8; ++nt) {
                const int t0 = nh * 64 + nt * 8 + 2 * tg;
                const float bf0 = s_bias[t0], bf1 = s_bias[t0 + 1];
                u64 wa[8], wb[8];
                {
                    const ulonglong2* w1a = reinterpret_cast<const ulonglong2*>(s_W1 + t0 * W1P);
                    const ulonglong2* w1b = reinterpret_cast<const ulonglong2*>(s_W1 + (t0 + 1) * W1P);
#pragma unroll
                    for (int q = 0; q < 4; ++q) {
                        ulonglong2 ta = w1a[q], tb = w1b[q];
                        wa[2*q] = ta.x; wa[2*q+1] = ta.y;
                        wb[2*q] = tb.x; wb[2*q+1] = tb.y;
                    }
                }
#pragma unroll
                for (int m = 0; m < 2; ++m) {
                    u64 H00 = pack2dup(fmaxf(acc[m][nt][0] + bf0, 0.0f));
                    u64 H01 = pack2dup(fmaxf(acc[m][nt][1] + bf1, 0.0f));
                    u64 H10 = pack2dup(fmaxf(acc[m][nt][2] + bf0, 0.0f));
                    u64 H11 = pack2dup(fmaxf(acc[m][nt][3] + bf1, 0.0f));
#pragma unroll
                    for (int j = 0; j < 8; ++j) {
                        ffma2(dx2[m][0][j], H00, wa[j]);
                        ffma2(dx2[m][0][j], H01, wb[j]);
                        ffma2(dx2[m][1][j], H10, wa[j]);
                        ffma2(dx2[m][1][j], H11, wb[j]);
                    }
                }
            }
        }

        // ---- quad reduce + stage dx ----
#pragma unroll
        for (int m = 0; m < 2; ++m) {
#pragma unroll
            for (int r = 0; r < 2; ++r) {
                float red[16];
#pragma unroll
                for (int j = 0; j < 8; ++j) {
                    float2 f = unpack2(dx2[m][r][j]);
                    red[2*j] = f.x; red[2*j+1] = f.y;
                }
#pragma unroll
                for (int o = 0; o < 16; ++o) {
                    red[o] += __shfl_xor_sync(0xffffffffu, red[o], 1);
                    red[o] += __shfl_xor_sync(0xffffffffu, red[o], 2);
                }
                if (tg == 0) {
                    const int row = R + m * 16 + r * 8 + g;
                    float* d = s_DX + row * W1P;
                    *reinterpret_cast<float4*>(d +  0) = make_float4(red[0],  red[1],  red[2],  red[3]);
                    *reinterpret_cast<float4*>(d +  4) = make_float4(red[4],  red[5],  red[6],  red[7]);
                    *reinterpret_cast<float4*>(d +  8) = make_float4(red[8],  red[9],  red[10], red[11]);
                    *reinterpret_cast<float4*>(d + 12) = make_float4(red[12], red[13], red[14], red[15]);
                }
            }
        }
        __syncwarp();

        // ---- residual update + store ----
        if (i < count) {
            const float* dxr = s_DX + tid * W1P;
            float outv[CCH];
#pragma unroll
            for (int c = 0; c < CCH; ++c)
                outv[c] = (c < 3) ? cen[c] : (cen[c] + dxr[c]);
            float4* dst = reinterpret_cast<float4*>(nxt + ((size_t)p << 4));
            dst[0] = make_float4(outv[0],  outv[1],  outv[2],  outv[3]);
            dst[1] = make_float4(outv[4],  outv[5],  outv[6],  outv[7]);
            dst[2] = make_float4(outv[8],  outv[9],  outv[10], outv[11]);
            dst[3] = make_float4(outv[12], outv[13], outv[14], outv[15]);
        }
        __syncwarp();
    }

    // ---- inactive copy-through ----
    const int icnt = g_icnt[step];
    const int* il = g_ilist[step];
    for (int i = blockIdx.x * 256 + tid; i < icnt; i += NSM_BLOCKS * 256) {
        int p = il[i];
        const float4* s = reinterpret_cast<const float4*>(cur + ((size_t)p << 4));
        float4* d = reinterpret_cast<float4*>(nxt + ((size_t)p << 4));
        d[0] = s[0]; d[1] = s[1]; d[2] = s[2]; d[3] = s[3];
    }
}

// ---------------------------------------------------------------------------
// Launch
// ---------------------------------------------------------------------------
extern "C" void kernel_launch(void* const* d_in, const int* in_sizes, int n_in,
                              void* d_out, int out_size)
{
    const float* x      = (const float*)d_in[0];
    const float* w_p0   = (const float*)d_in[1];
    const float* w_p1   = (const float*)d_in[2];
    const float* w_fc0  = (const float*)d_in[3];
    const float* b_fc0  = (const float*)d_in[4];
    const float* w_fc1  = (const float*)d_in[5];
    float* out = (float*)d_out;

    KeyArr keys;
    for (int j = 0; j < STEPS; ++j) {
        uint32_t a, b;
        threefry2x32(0u, 42u, 0u, (uint32_t)j, a, b);
        keys.k0[j] = a; keys.k1[j] = b;
    }

    cudaFuncSetAttribute(nca_step_mma,
                         cudaFuncAttributeMaxDynamicSharedMemorySize, SM_BYTES);

    nca_pack_kernel<<<NPIX / 256, 256>>>(x);
    nca_maskall_kernel<<<NPIX / 256, 256>>>(keys);
    nca_prep_kernel<<<(HID * 48 + 255) / 256, 256>>>(w_fc0);
    for (int s = 0; s < STEPS; ++s) {
        nca_step_mma<<<NSM_BLOCKS, 256, SM_BYTES>>>(
            s & 1, s, w_p0, w_p1, b_fc0, w_fc1);
    }
    nca_unpack_kernel<<<NPIX / 256, 256>>>(out);
}